// round 8
// baseline (speedup 1.0000x reference)
#include <cuda_runtime.h>

// SphericalBessel, Miller downward recurrence in scaled variable
//   S_l = j_l * (x*sigma)^(-l),  sigma = exact per-thread power of two.
// Branch-free recurrence  S_{l-1} = (2l+1)*sigma*S_l - (x*sigma)^2*S_{l+1},
// double-single (unnormalized pair) arithmetic.
//
// R8: y[] taps in shared memory AND __launch_bounds__(256, 6) forcing
// regs<=42 -> 48 warps/SM (12/SMSP) to cover the ~8-deep FFMA dependency
// chain per step (single-warp ILP ~0.5 -> need ~8+ eligible warps/SMSP).
//
// Thread = one (n,k). Warp = one n, k=0..31 -> coalesced 128B stores per l.

#define NPTS   65536
#define KMAX   32
#define LMAX   32
#define LSTART 49   // L_MAX + int(sqrt(10*L_MAX)) = 32 + 17
#define BLK    256

// a + b and a - b as FFMA with immediate +-1.0 multiplier.
__device__ __forceinline__ float fa(float a, float b) {
    float d; asm("fma.rn.f32 %0,%1,0f3F800000,%2;" : "=f"(d) : "f"(a), "f"(b)); return d;
}
__device__ __forceinline__ float fs(float a, float b) {  // a - b
    float d; asm("fma.rn.f32 %0,%1,0fBF800000,%2;" : "=f"(d) : "f"(b), "f"(a)); return d;
}

__global__ void __launch_bounds__(BLK, 6)
sph_bessel_sm6(const float* __restrict__ r, float* __restrict__ out) {
    __shared__ float ysm[LMAX - 1][BLK];  // taps l=1..31, conflict-free

    int tid = blockIdx.x * BLK + threadIdx.x;
    int lt  = threadIdx.x;
    int n  = tid >> 5;
    int kk = tid & 31;                    // k = kk+1
    float kf = (float)(kk + 1);
    float rv = __ldg(&r[n]);

    // exact DS x = r*k
    float xh = rv * kf;
    float xl = fmaf(rv, kf, -xh);

    // sigma = 0.25 / 2^floor(log2 max(x,99)) via exponent bits (exact pow2)
    float m = fmaxf(xh, 99.0f);
    int pb = __float_as_int(m) & 0x7f800000;
    float sigma = __int_as_float(0x7E000000 - pb);

    // z = x*sigma (exact), X2 = z^2 as DS
    float zh = xh * sigma, zl = xl * sigma;
    float X2h = zh * zh;
    float X2l = fmaf(zh, zh, -X2h);
    X2l = fmaf(zh, 2.0f * zl, X2l);
    X2l = fmaf(zl, zl, X2l);

    // state: A = S_l, B = S_{l+1}, unnormalized DS pairs. Init (2^70, 0).
    float Ah = 0x1p70f, Al = 0.0f, Bh = 0.0f, Bl = 0.0f;
    float y0 = 0.0f;

    #pragma unroll
    for (int i = LSTART; i >= 1; --i) {
        float cs = (float)(2 * i + 1) * sigma;   // exact (int<=99 * pow2)

        // t = cs (x) A   (DS product, exact residual)
        float th = cs * Ah;
        float te = fmaf(cs, Ah, -th);
        te = fmaf(cs, Al, te);

        // u = X2 (x) B
        float uh = X2h * Bh;
        float ue = fmaf(X2h, Bh, -uh);
        ue = fmaf(X2h, Bl, ue);
        ue = fmaf(X2l, Bh, ue);

        // C = t - u : branchless Knuth two-sum of (th, -uh)
        float sh = fs(th, uh);
        float v  = fs(sh, th);
        float w  = fs(sh, v);
        float e1 = fs(th, w);
        float t1 = fa(uh, v);
        float er = fs(e1, t1);
        float lo = fa(er, te);
        lo = fs(lo, ue);

        Bh = Ah; Bl = Al;
        Ah = sh; Al = lo;

        if (i == 1)         y0 = fa(sh, lo);       // DS-rounded: feeds 1/y0
        else if (i <= LMAX) ysm[i - 2][lt] = sh;   // taps l = i-1 in [1,31]
    }

    // normalization: true j0 = sin(x)/x (MUFU), x_lo phase compensation.
    float s, cc;
    __sincosf(xh, &s, &cc);
    s = fmaf(xl, cc, s);
    float norm = __fdividef(s * (0.7978845608028654f * kf), xh * y0);

    float* o = out + (size_t)n * (LMAX * KMAX) + kk;
    o[0] = y0 * norm;                     // l = 0
    norm *= zh;
    #pragma unroll
    for (int l = 1; l < LMAX; ++l) {
        o[(size_t)l * KMAX] = ysm[l - 1][lt] * norm;  // coalesced 128B per l
        norm *= zh;                                    // z^l chain (<=31 ulp)
    }
}

extern "C" void kernel_launch(void* const* d_in, const int* in_sizes, int n_in,
                              void* d_out, int out_size) {
    const float* r = (const float*)d_in[0];
    float* out = (float*)d_out;
    int total = NPTS * KMAX;                  // 2,097,152 threads
    sph_bessel_sm6<<<total / BLK, BLK>>>(r, out);
}

// round 9
// speedup vs baseline: 1.0235x; 1.0235x over previous
#include <cuda_runtime.h>

// SphericalBessel, Miller downward recurrence in scaled variable
//   S_l = j_l * (x*sigma)^(-l),  sigma = exact per-thread power of two.
// Branch-free recurrence  S_{l-1} = (2l+1)*sigma*S_l - (x*sigma)^2*S_{l+1},
// double-single (unnormalized pair) arithmetic. Taps in REGISTERS (R5 core).
//
// R9: epilogue stores go to a 32KB shared staging buffer (conflict-free
// STS.32, ~2cyc issue) and ONE cp.async.bulk per block copies the block's
// CONTIGUOUS 32KB gmem span (out[n0..n0+7][:][:]) -> removes 32 STG.32
// (5cyc issue each) from the per-thread issue budget.
//
// Thread = one (n,k). Warp = one n, k=0..31. Block = 8 consecutive n.

#define NPTS   65536
#define KMAX   32
#define LMAX   32
#define LSTART 49   // L_MAX + int(sqrt(10*L_MAX)) = 32 + 17
#define BLK    256

// a + b and a - b as FFMA with immediate +-1.0 multiplier.
__device__ __forceinline__ float fa(float a, float b) {
    float d; asm("fma.rn.f32 %0,%1,0f3F800000,%2;" : "=f"(d) : "f"(a), "f"(b)); return d;
}
__device__ __forceinline__ float fs(float a, float b) {  // a - b
    float d; asm("fma.rn.f32 %0,%1,0fBF800000,%2;" : "=f"(d) : "f"(b), "f"(a)); return d;
}

__global__ void __launch_bounds__(BLK)
sph_bessel_tma(const float* __restrict__ r, float* __restrict__ out) {
    __shared__ float stage[8][LMAX][KMAX];   // 32KB, gmem byte order

    int tid = blockIdx.x * BLK + threadIdx.x;
    int w   = threadIdx.x >> 5;           // local n (warp id)
    int kk  = threadIdx.x & 31;           // k = kk+1
    int n   = tid >> 5;
    float kf = (float)(kk + 1);
    float rv = __ldg(&r[n]);

    // exact DS x = r*k
    float xh = rv * kf;
    float xl = fmaf(rv, kf, -xh);

    // sigma = 0.25 / 2^floor(log2 max(x,99)) via exponent bits (exact pow2)
    float m = fmaxf(xh, 99.0f);
    int pb = __float_as_int(m) & 0x7f800000;
    float sigma = __int_as_float(0x7E000000 - pb);

    // z = x*sigma (exact), X2 = z^2 as DS
    float zh = xh * sigma, zl = xl * sigma;
    float X2h = zh * zh;
    float X2l = fmaf(zh, zh, -X2h);
    X2l = fmaf(zh, 2.0f * zl, X2l);
    X2l = fmaf(zl, zl, X2l);

    // state: A = S_l, B = S_{l+1}, unnormalized DS pairs. Init (2^70, 0).
    float Ah = 0x1p70f, Al = 0.0f, Bh = 0.0f, Bl = 0.0f;
    float y[LMAX];
    float y0 = 0.0f;

    #pragma unroll
    for (int i = LSTART; i >= 1; --i) {
        float cs = (float)(2 * i + 1) * sigma;   // exact (int<=99 * pow2)

        // t = cs (x) A   (DS product, exact residual)
        float th = cs * Ah;
        float te = fmaf(cs, Ah, -th);
        te = fmaf(cs, Al, te);

        // u = X2 (x) B
        float uh = X2h * Bh;
        float ue = fmaf(X2h, Bh, -uh);
        ue = fmaf(X2h, Bl, ue);
        ue = fmaf(X2l, Bh, ue);

        // C = t - u : branchless Knuth two-sum of (th, -uh)
        float sh = fs(th, uh);
        float v  = fs(sh, th);
        float ww = fs(sh, v);
        float e1 = fs(th, ww);
        float t1 = fa(uh, v);
        float er = fs(e1, t1);
        float lo = fa(er, te);
        lo = fs(lo, ue);

        Bh = Ah; Bl = Al;
        Ah = sh; Al = lo;

        if (i == 1)         y0 = fa(sh, lo);   // DS-rounded: feeds 1/y0
        else if (i <= LMAX) y[i - 1] = sh;     // reg tap (rename, free)
    }
    y[0] = y0;

    // normalization: true j0 = sin(x)/x (MUFU), x_lo phase compensation.
    float s, cc;
    __sincosf(xh, &s, &cc);
    s = fmaf(xl, cc, s);
    float norm = __fdividef(s * (0.7978845608028654f * kf), xh * y0);

    // scaled outputs -> shared staging (conflict-free: lane == bank)
    #pragma unroll
    for (int l = 0; l < LMAX; ++l) {
        stage[w][l][kk] = y[l] * norm;
        norm *= zh;                           // z^l chain (<=31 ulp)
    }

    __syncthreads();

    // one bulk async copy: block's 32KB is contiguous at out + blockIdx*8192 floats
    if (threadIdx.x == 0) {
        asm volatile("fence.proxy.async.shared::cta;" ::: "memory");
        unsigned long long gdst = (unsigned long long)(out) +
                                  (unsigned long long)blockIdx.x * (8u * LMAX * KMAX * 4u);
        unsigned int ssrc;
        asm("{ .reg .u64 t; cvta.to.shared.u64 t, %1; cvt.u32.u64 %0, t; }"
            : "=r"(ssrc) : "l"(&stage[0][0][0]));
        asm volatile(
            "cp.async.bulk.global.shared::cta.bulk_group [%0], [%1], %2;"
            :: "l"(gdst), "r"(ssrc), "r"(8u * LMAX * KMAX * 4u) : "memory");
        asm volatile("cp.async.bulk.commit_group;" ::: "memory");
        asm volatile("cp.async.bulk.wait_group.read 0;" ::: "memory");
    }
}

extern "C" void kernel_launch(void* const* d_in, const int* in_sizes, int n_in,
                              void* d_out, int out_size) {
    const float* r = (const float*)d_in[0];
    float* out = (float*)d_out;
    int total = NPTS * KMAX;                  // 2,097,152 threads
    sph_bessel_tma<<<total / BLK, BLK>>>(r, out);
}

// round 10
// speedup vs baseline: 1.0988x; 1.0735x over previous
#include <cuda_runtime.h>

// SphericalBessel, Miller downward recurrence in scaled variable
//   S_l = j_l * (x*sigma)^(-l),  sigma = exact per-thread power of two.
// Branch-free recurrence  S_{l-1} = (2l+1)*sigma*S_l - (x*sigma)^2*S_{l+1},
// double-single (unnormalized pair) arithmetic. Register taps (R5 layout).
//
// R10: the error-free addition th + (-uh) uses a SELECT-ORDERED Dekker
// fast2sum: FSETP/FSEL run on the pred/alu pipes (idle), leaving only
// 3 FFMA-imm on the fma pipe instead of Knuth's 6. Exact (|big|>=|small|).
// fma-pipe cycles/step: 23 -> 20.
//
// Thread = one (n,k). Warp = one n, k=0..31 -> coalesced 128B stores per l.

#define NPTS   65536
#define KMAX   32
#define LMAX   32
#define LSTART 49   // L_MAX + int(sqrt(10*L_MAX)) = 32 + 17
#define BLK    256

// a + b and a - b as FFMA with immediate +-1.0 multiplier (rt_SMSP = 1).
__device__ __forceinline__ float fa(float a, float b) {
    float d; asm("fma.rn.f32 %0,%1,0f3F800000,%2;" : "=f"(d) : "f"(a), "f"(b)); return d;
}
__device__ __forceinline__ float fs(float a, float b) {  // a - b
    float d; asm("fma.rn.f32 %0,%1,0fBF800000,%2;" : "=f"(d) : "f"(b), "f"(a)); return d;
}

__global__ void __launch_bounds__(BLK)
sph_bessel_f2s(const float* __restrict__ r, float* __restrict__ out) {
    int tid = blockIdx.x * BLK + threadIdx.x;
    int n  = tid >> 5;
    int kk = tid & 31;                    // k = kk+1
    float kf = (float)(kk + 1);
    float rv = __ldg(&r[n]);

    // exact DS x = r*k
    float xh = rv * kf;
    float xl = fmaf(rv, kf, -xh);

    // sigma = 0.25 / 2^floor(log2 max(x,99)) via exponent bits (exact pow2)
    float m = fmaxf(xh, 99.0f);
    int pb = __float_as_int(m) & 0x7f800000;
    float sigma = __int_as_float(0x7E000000 - pb);

    // z = x*sigma (exact), X2 = z^2 as DS
    float zh = xh * sigma, zl = xl * sigma;
    float X2h = zh * zh;
    float X2l = fmaf(zh, zh, -X2h);
    X2l = fmaf(zh, 2.0f * zl, X2l);
    X2l = fmaf(zl, zl, X2l);

    // state: A = S_l, B = S_{l+1}, unnormalized DS pairs. Init (2^70, 0).
    float Ah = 0x1p70f, Al = 0.0f, Bh = 0.0f, Bl = 0.0f;
    float y[LMAX];
    float y0 = 0.0f;

    #pragma unroll
    for (int i = LSTART; i >= 1; --i) {
        float cs = (float)(2 * i + 1) * sigma;   // exact (int<=99 * pow2)

        // t = cs (x) A   (DS product, exact residual)
        float th = cs * Ah;
        float te = fmaf(cs, Ah, -th);
        te = fmaf(cs, Al, te);

        // u = X2 (x) B  (negated via -X2? keep positive, subtract below)
        float uh = X2h * Bh;
        float ue = fmaf(X2h, Bh, -uh);
        ue = fmaf(X2h, Bl, ue);
        ue = fmaf(X2l, Bh, ue);

        // C = th - uh exactly, via select-ordered Dekker fast2sum.
        // nu = -uh (exact negation folds into the select operands).
        float nu  = -uh;                        // sign flip: free/alu
        bool  p   = fabsf(th) >= fabsf(uh);     // FSETP (pred pipe)
        float big = p ? th : nu;                // FSEL (alu)
        float sml = p ? nu : th;                // FSEL (alu)
        float sh  = fa(big, sml);               // s   = big + small
        float zz  = fs(sh, big);                // z   = s - big
        float er  = fs(sml, zz);                // err = small - z  (exact)
        float lo  = fa(er, te);
        lo = fs(lo, ue);

        Bh = Ah; Bl = Al;
        Ah = sh; Al = lo;

        if (i == 1)         y0 = fa(sh, lo);   // DS-rounded: feeds 1/y0
        else if (i <= LMAX) y[i - 1] = sh;     // reg tap (rename, free)
    }
    y[0] = y0;

    // normalization: true j0 = sin(x)/x (MUFU), x_lo phase compensation.
    float s, cc;
    __sincosf(xh, &s, &cc);
    s = fmaf(xl, cc, s);
    float norm = __fdividef(s * (0.7978845608028654f * kf), xh * y0);

    float* o = out + (size_t)n * (LMAX * KMAX) + kk;
    #pragma unroll
    for (int l = 0; l < LMAX; ++l) {
        o[(size_t)l * KMAX] = y[l] * norm;   // warp-coalesced 128B per l
        norm *= zh;                           // z^l chain (<=31 ulp)
    }
}

extern "C" void kernel_launch(void* const* d_in, const int* in_sizes, int n_in,
                              void* d_out, int out_size) {
    const float* r = (const float*)d_in[0];
    float* out = (float*)d_out;
    int total = NPTS * KMAX;                  // 2,097,152 threads
    sph_bessel_f2s<<<total / BLK, BLK>>>(r, out);
}